// round 1
// baseline (speedup 1.0000x reference)
#include <cuda_runtime.h>
#include <cuda_bf16.h>
#include <math.h>

// ---------------- problem constants ----------------
#define NN      15000      // nodes
#define NE      60000      // edges
#define DIN     74         // node in feats
#define DEI     12         // edge in feats
#define DD      64         // node_out_feats
#define EH      128        // edge hidden
#define NSTEPS  6
#define BN_EPS  1e-5f

// ---------------- scratch (device globals; allocation-free) ----------------
__device__ float g_H[NN * DD];                 // hidden / h (3.84 MB)
__device__ float g_A[NE * EH];                 // edge hidden a (30 MB)
__device__ float g_EW[(size_t)NE * DD * DD];   // per-edge matrices, fp32 (983 MB)
__device__ float g_RST[NN * DD];               // aggregation buffer
__device__ float g_deg[NN];
__device__ float g_invdeg[NN];
__device__ float g_colsum[DD];
__device__ float g_colsq[DD];
__device__ float g_bnscale[DD];
__device__ float g_bnshift[DD];

// ---------------- f32x2 packed-FMA helpers (Blackwell FFMA2) ----------------
__device__ __forceinline__ unsigned long long pack2(float x, float y) {
    unsigned long long r;
    asm("mov.b64 %0, {%1, %2};" : "=l"(r) : "f"(x), "f"(y));
    return r;
}
__device__ __forceinline__ unsigned long long fma2(unsigned long long a,
                                                   unsigned long long b,
                                                   unsigned long long c) {
    unsigned long long d;
    asm("fma.rn.f32x2 %0, %1, %2, %3;" : "=l"(d) : "l"(a), "l"(b), "l"(c));
    return d;
}
__device__ __forceinline__ float2 unpack2(unsigned long long v) {
    float2 f;
    asm("mov.b64 {%0, %1}, %2;" : "=f"(f.x), "=f"(f.y) : "l"(v));
    return f;
}

// ---------------- small kernels ----------------
__global__ void k_zero_deg() {
    int i = blockIdx.x * blockDim.x + threadIdx.x;
    if (i < NN) g_deg[i] = 0.f;
}

__global__ void k_deg(const int* __restrict__ dst) {
    int e = blockIdx.x * blockDim.x + threadIdx.x;
    if (e < NE) atomicAdd(&g_deg[dst[e]], 1.f);
}

__global__ void k_invdeg() {
    int i = blockIdx.x * blockDim.x + threadIdx.x;
    if (i < NN) {
        float d = g_deg[i];
        g_invdeg[i] = (d > 0.f) ? (1.f / d) : 0.f;
    }
}

// h = relu(node_feats @ W_proj + b_proj); one row per block, one col per thread
__global__ void k_proj(const float* __restrict__ nf, const float* __restrict__ Wp,
                       const float* __restrict__ bp) {
    int r = blockIdx.x;
    int o = threadIdx.x;
    const float* row = nf + (size_t)r * DIN;
    float acc = bp[o];
#pragma unroll 2
    for (int i = 0; i < DIN; ++i)
        acc = fmaf(__ldg(&row[i]), __ldg(&Wp[i * DD + o]), acc);
    g_H[(size_t)r * DD + o] = fmaxf(acc, 0.f);
}

// a = relu(edge_feats @ W_e1 + b_e1)
__global__ void k_edge1(const float* __restrict__ ef, const float* __restrict__ W1,
                        const float* __restrict__ b1) {
    int e = blockIdx.x;
    int k = threadIdx.x;
    const float* row = ef + (size_t)e * DEI;
    float acc = b1[k];
#pragma unroll
    for (int i = 0; i < DEI; ++i)
        acc = fmaf(__ldg(&row[i]), __ldg(&W1[i * EH + k]), acc);
    g_A[(size_t)e * EH + k] = fmaxf(acc, 0.f);
}

// ---------------- edge MLP stage 2: EW = a @ W_e2 + b_e2 (fp32, FFMA2) ------
// tile: 128 edges x 128 cols, block 256 = 16(tx: col groups of 8) x 16(ty: edge groups of 8)
#define E2_SMEM_BYTES (128 * 132 * 4)
__global__ void __launch_bounds__(256) k_edge2(const float* __restrict__ W2,
                                               const float* __restrict__ b2) {
    extern __shared__ float AsT[];   // [k=128][edge pad 132]
    int tid = threadIdx.x;
    int tx = tid & 15;               // col group
    int ty = tid >> 4;               // edge group
    int e0 = blockIdx.x * 128;
    int c0 = blockIdx.y * 128;
    int cbase = c0 + tx * 8;

    // stage A tile transposed: AsT[k][e_local]
    for (int idx = tid; idx < 128 * 128; idx += 256) {
        int el = idx >> 7;
        int kk = idx & 127;
        int e = e0 + el;
        AsT[kk * 132 + el] = (e < NE) ? g_A[(size_t)e * EH + kk] : 0.f;
    }
    __syncthreads();

    unsigned long long acc[8][4];
#pragma unroll
    for (int j = 0; j < 8; ++j)
#pragma unroll
        for (int p = 0; p < 4; ++p) acc[j][p] = 0ull;

#pragma unroll 2
    for (int k = 0; k < 128; ++k) {
        const float* arow = &AsT[k * 132 + ty * 8];
        float4 a0 = *reinterpret_cast<const float4*>(arow);
        float4 a1 = *reinterpret_cast<const float4*>(arow + 4);
        unsigned long long ap[8];
        ap[0] = pack2(a0.x, a0.x); ap[1] = pack2(a0.y, a0.y);
        ap[2] = pack2(a0.z, a0.z); ap[3] = pack2(a0.w, a0.w);
        ap[4] = pack2(a1.x, a1.x); ap[5] = pack2(a1.y, a1.y);
        ap[6] = pack2(a1.z, a1.z); ap[7] = pack2(a1.w, a1.w);

        const float* wrow = W2 + ((size_t)k << 12) + cbase;
        ulonglong2 wA = *reinterpret_cast<const ulonglong2*>(wrow);
        ulonglong2 wB = *reinterpret_cast<const ulonglong2*>(wrow + 4);
#pragma unroll
        for (int j = 0; j < 8; ++j) {
            acc[j][0] = fma2(ap[j], wA.x, acc[j][0]);
            acc[j][1] = fma2(ap[j], wA.y, acc[j][1]);
            acc[j][2] = fma2(ap[j], wB.x, acc[j][2]);
            acc[j][3] = fma2(ap[j], wB.y, acc[j][3]);
        }
    }

    float4 bA = *reinterpret_cast<const float4*>(b2 + cbase);
    float4 bB = *reinterpret_cast<const float4*>(b2 + cbase + 4);
#pragma unroll
    for (int j = 0; j < 8; ++j) {
        int e = e0 + ty * 8 + j;
        if (e < NE) {
            float2 p0 = unpack2(acc[j][0]);
            float2 p1 = unpack2(acc[j][1]);
            float2 p2 = unpack2(acc[j][2]);
            float2 p3 = unpack2(acc[j][3]);
            float4 o0 = make_float4(p0.x + bA.x, p0.y + bA.y, p1.x + bA.z, p1.y + bA.w);
            float4 o1 = make_float4(p2.x + bB.x, p2.y + bB.y, p3.x + bB.z, p3.y + bB.w);
            float4* orow = reinterpret_cast<float4*>(g_EW + (size_t)e * 4096 + cbase);
            orow[0] = o0;
            orow[1] = o1;
        }
    }
}

// ---------------- per-step kernels ----------------
__global__ void k_zero_rst() {
    int i = blockIdx.x * blockDim.x + threadIdx.x;
    if (i < NN * DD) g_RST[i] = 0.f;
    if (i < DD) { g_colsum[i] = 0.f; g_colsq[i] = 0.f; }
}

// msg[e] = h[src[e]] @ EW[e]; scatter-add into RST[dst[e]]. One warp per edge.
__global__ void __launch_bounds__(256) k_msg(const int* __restrict__ src,
                                             const int* __restrict__ dst) {
    __shared__ float hbuf[8][64];
    int w = threadIdx.x >> 5;
    int lane = threadIdx.x & 31;
    int e = blockIdx.x * 8 + w;
    if (e >= NE) return;
    int s = src[e];
    int d = dst[e];
    hbuf[w][lane]      = g_H[(size_t)s * DD + lane];
    hbuf[w][lane + 32] = g_H[(size_t)s * DD + 32 + lane];
    __syncwarp();

    const float4* M = reinterpret_cast<const float4*>(g_EW + (size_t)e * 4096);
    int sub = lane >> 4;   // row parity
    int q   = lane & 15;   // col group (4 cols)
    float4 acc = make_float4(0.f, 0.f, 0.f, 0.f);
#pragma unroll
    for (int t = 0; t < 32; ++t) {
        int i = 2 * t + sub;
        float hv = hbuf[w][i];
        float4 mv = M[i * 16 + q];
        acc.x = fmaf(hv, mv.x, acc.x);
        acc.y = fmaf(hv, mv.y, acc.y);
        acc.z = fmaf(hv, mv.z, acc.z);
        acc.w = fmaf(hv, mv.w, acc.w);
    }
    acc.x += __shfl_xor_sync(0xffffffffu, acc.x, 16);
    acc.y += __shfl_xor_sync(0xffffffffu, acc.y, 16);
    acc.z += __shfl_xor_sync(0xffffffffu, acc.z, 16);
    acc.w += __shfl_xor_sync(0xffffffffu, acc.w, 16);
    if (sub == 0) {
        float* r = g_RST + (size_t)d * DD + q * 4;
        atomicAdd(r + 0, acc.x);
        atomicAdd(r + 1, acc.y);
        atomicAdd(r + 2, acc.z);
        atomicAdd(r + 3, acc.w);
    }
}

// rst = rst*invdeg + conv_bias (written back) + per-column sum/sumsq
__global__ void k_bnred(const float* __restrict__ cbias) {
    int o = threadIdx.x & 63;
    int ty = threadIdx.x >> 6;    // 0..3
    int v0 = blockIdx.x * 128;
    float cb = cbias[o];
    float s = 0.f, s2 = 0.f;
#pragma unroll 4
    for (int t = 0; t < 32; ++t) {
        int v = v0 + ty + t * 4;
        if (v < NN) {
            size_t idx = (size_t)v * DD + o;
            float x = fmaf(g_RST[idx], g_invdeg[v], cb);
            g_RST[idx] = x;
            s += x;
            s2 = fmaf(x, x, s2);
        }
    }
    __shared__ float ss[4][64], ss2[4][64];
    ss[ty][o] = s;
    ss2[ty][o] = s2;
    __syncthreads();
    if (ty == 0) {
        s  = ss[0][o] + ss[1][o] + ss[2][o] + ss[3][o];
        s2 = ss2[0][o] + ss2[1][o] + ss2[2][o] + ss2[3][o];
        atomicAdd(&g_colsum[o], s);
        atomicAdd(&g_colsq[o], s2);
    }
}

__global__ void k_bnfin(const float* __restrict__ gamma, const float* __restrict__ beta) {
    int o = threadIdx.x;
    const float invn = 1.f / (float)NN;
    float mu = g_colsum[o] * invn;
    float var = g_colsq[o] * invn - mu * mu;
    float sc = gamma[o] * rsqrtf(var + BN_EPS);
    g_bnscale[o] = sc;
    g_bnshift[o] = beta[o] - mu * sc;
}

// GRU cell for 64 nodes per block; W rows live in registers (FFMA2 pairs)
__global__ void __launch_bounds__(192) k_gru(const float* __restrict__ W_ih,
                                             const float* __restrict__ W_hh,
                                             const float* __restrict__ b_ih,
                                             const float* __restrict__ b_hh) {
    __shared__ float m_s[64], h_s[64], gi_s[192], gh_s[192];
    int j = threadIdx.x;

    unsigned long long wih[32], whh[32];
    const unsigned long long* pih = reinterpret_cast<const unsigned long long*>(W_ih) + j * 32;
    const unsigned long long* phh = reinterpret_cast<const unsigned long long*>(W_hh) + j * 32;
#pragma unroll
    for (int q = 0; q < 32; ++q) { wih[q] = pih[q]; whh[q] = phh[q]; }
    float bi = b_ih[j], bh = b_hh[j];
    float sc = 0.f, sh = 0.f;
    if (j < 64) { sc = g_bnscale[j]; sh = g_bnshift[j]; }

    int v0 = blockIdx.x * 64;
    for (int n = 0; n < 64; ++n) {
        int v = v0 + n;
        if (v >= NN) break;                         // uniform across block
        if (j < 64) {
            float x = g_RST[(size_t)v * DD + j];
            m_s[j] = fmaxf(fmaf(x, sc, sh), 0.f);   // BN affine + ReLU
        } else if (j < 128) {
            h_s[j - 64] = g_H[(size_t)v * DD + (j - 64)];
        }
        __syncthreads();

        unsigned long long gi2 = 0ull, gh2 = 0ull;
        const unsigned long long* m2 = reinterpret_cast<const unsigned long long*>(m_s);
        const unsigned long long* h2 = reinterpret_cast<const unsigned long long*>(h_s);
#pragma unroll
        for (int q = 0; q < 32; ++q) {
            gi2 = fma2(m2[q], wih[q], gi2);
            gh2 = fma2(h2[q], whh[q], gh2);
        }
        float2 gi = unpack2(gi2);
        float2 gh = unpack2(gh2);
        gi_s[j] = gi.x + gi.y + bi;
        gh_s[j] = gh.x + gh.y + bh;
        __syncthreads();

        if (j < 64) {
            float r = 1.f / (1.f + expf(-(gi_s[j] + gh_s[j])));
            float z = 1.f / (1.f + expf(-(gi_s[64 + j] + gh_s[64 + j])));
            float nn = tanhf(gi_s[128 + j] + r * gh_s[128 + j]);
            g_H[(size_t)v * DD + j] = (1.f - z) * nn + z * h_s[j];
        }
        __syncthreads();
    }
}

__global__ void k_copy(float* __restrict__ out) {
    int i = blockIdx.x * blockDim.x + threadIdx.x;
    if (i < NN * DD) out[i] = g_H[i];
}

// ---------------- launch ----------------
extern "C" void kernel_launch(void* const* d_in, const int* in_sizes, int n_in,
                              void* d_out, int out_size) {
    const float *node_feats = nullptr, *edge_feats = nullptr;
    const float *W_proj = nullptr, *b_proj = nullptr;
    const float *W_e1 = nullptr, *b_e1 = nullptr, *W_e2 = nullptr, *b_e2 = nullptr;
    const float *conv_bias = nullptr, *bn_gamma = nullptr, *bn_beta = nullptr;
    const float *W_ih = nullptr, *W_hh = nullptr, *b_ih = nullptr, *b_hh = nullptr;
    const int *src = nullptr, *dst = nullptr;
    int c60000 = 0, c64 = 0, c12288 = 0, c192 = 0;

    for (int i = 0; i < n_in; ++i) {
        const void* p = d_in[i];
        switch (in_sizes[i]) {
            case 1110000: node_feats = (const float*)p; break;
            case 720000:  edge_feats = (const float*)p; break;
            case 60000:   if (c60000++ == 0) src = (const int*)p; else dst = (const int*)p; break;
            case 4736:    W_proj = (const float*)p; break;
            case 64:
                if (c64 == 0) b_proj = (const float*)p;
                else if (c64 == 1) conv_bias = (const float*)p;
                else if (c64 == 2) bn_gamma = (const float*)p;
                else bn_beta = (const float*)p;
                ++c64; break;
            case 1536:    W_e1 = (const float*)p; break;
            case 128:     b_e1 = (const float*)p; break;
            case 524288:  W_e2 = (const float*)p; break;
            case 4096:    b_e2 = (const float*)p; break;
            case 12288:   if (c12288++ == 0) W_ih = (const float*)p; else W_hh = (const float*)p; break;
            case 192:     if (c192++ == 0) b_ih = (const float*)p; else b_hh = (const float*)p; break;
            default: break;
        }
    }
    if (!node_feats || !edge_feats || !src || !dst || !W_proj || !b_proj || !W_e1 ||
        !b_e1 || !W_e2 || !b_e2 || !conv_bias || !bn_gamma || !bn_beta || !W_ih ||
        !W_hh || !b_ih || !b_hh)
        return;

    cudaFuncSetAttribute(k_edge2, cudaFuncAttributeMaxDynamicSharedMemorySize, E2_SMEM_BYTES);

    // degree + inverse
    k_zero_deg<<<(NN + 255) / 256, 256>>>();
    k_deg<<<(NE + 255) / 256, 256>>>(dst);
    k_invdeg<<<(NN + 255) / 256, 256>>>();

    // static precompute
    k_proj<<<NN, DD>>>(node_feats, W_proj, b_proj);
    k_edge1<<<NE, EH>>>(edge_feats, W_e1, b_e1);
    k_edge2<<<dim3((NE + 127) / 128, 32), 256, E2_SMEM_BYTES>>>(W_e2, b_e2);

    // message-passing steps
    for (int s = 0; s < NSTEPS; ++s) {
        k_zero_rst<<<(NN * DD + 255) / 256, 256>>>();
        k_msg<<<(NE + 7) / 8, 256>>>(src, dst);
        k_bnred<<<(NN + 127) / 128, 256>>>(conv_bias);
        k_bnfin<<<1, 64>>>(bn_gamma, bn_beta);
        k_gru<<<(NN + 63) / 64, 192>>>(W_ih, W_hh, b_ih, b_hh);
    }

    k_copy<<<(NN * DD + 255) / 256, 256>>>((float*)d_out);
}

// round 3
// speedup vs baseline: 1.2052x; 1.2052x over previous
#include <cuda_runtime.h>
#include <cuda_fp16.h>
#include <cuda_bf16.h>
#include <math.h>

// ---------------- problem constants ----------------
#define NN      15000      // nodes
#define NE      60000      // edges
#define DIN     74         // node in feats
#define DEI     12         // edge in feats
#define DD      64         // node_out_feats
#define EH      128        // edge hidden
#define NSTEPS  6
#define BN_EPS  1e-5f

// ---------------- scratch (device globals; allocation-free) ----------------
__device__ float  g_H[NN * DD];                  // hidden / h
__device__ float  g_A[NE * EH];                  // edge hidden a
__device__ __half g_EWh[(size_t)NE * DD * DD];   // per-edge matrices, fp16 (492 MB)
__device__ float  g_RST[NN * DD];                // aggregation buffer
__device__ float  g_deg[NN];
__device__ float  g_invdeg[NN];
__device__ float  g_colsum[DD];
__device__ float  g_colsq[DD];
__device__ float  g_bnscale[DD];
__device__ float  g_bnshift[DD];

// ---------------- f32x2 packed-FMA helpers (Blackwell FFMA2) ----------------
__device__ __forceinline__ unsigned long long pack2(float x, float y) {
    unsigned long long r;
    asm("mov.b64 %0, {%1, %2};" : "=l"(r) : "f"(x), "f"(y));
    return r;
}
__device__ __forceinline__ unsigned long long fma2(unsigned long long a,
                                                   unsigned long long b,
                                                   unsigned long long c) {
    unsigned long long d;
    asm("fma.rn.f32x2 %0, %1, %2, %3;" : "=l"(d) : "l"(a), "l"(b), "l"(c));
    return d;
}
__device__ __forceinline__ float2 unpack2(unsigned long long v) {
    float2 f;
    asm("mov.b64 {%0, %1}, %2;" : "=f"(f.x), "=f"(f.y) : "l"(v));
    return f;
}

// ---------------- small kernels ----------------
__global__ void k_zero_deg() {
    int i = blockIdx.x * blockDim.x + threadIdx.x;
    if (i < NN) g_deg[i] = 0.f;
}

__global__ void k_deg(const int* __restrict__ dst) {
    int e = blockIdx.x * blockDim.x + threadIdx.x;
    if (e < NE) atomicAdd(&g_deg[dst[e]], 1.f);
}

__global__ void k_invdeg() {
    int i = blockIdx.x * blockDim.x + threadIdx.x;
    if (i < NN) {
        float d = g_deg[i];
        g_invdeg[i] = (d > 0.f) ? (1.f / d) : 0.f;
    }
}

// h = relu(node_feats @ W_proj + b_proj)
__global__ void k_proj(const float* __restrict__ nf, const float* __restrict__ Wp,
                       const float* __restrict__ bp) {
    int r = blockIdx.x;
    int o = threadIdx.x;
    const float* row = nf + (size_t)r * DIN;
    float acc = bp[o];
#pragma unroll 2
    for (int i = 0; i < DIN; ++i)
        acc = fmaf(__ldg(&row[i]), __ldg(&Wp[i * DD + o]), acc);
    g_H[(size_t)r * DD + o] = fmaxf(acc, 0.f);
}

// a = relu(edge_feats @ W_e1 + b_e1)
__global__ void k_edge1(const float* __restrict__ ef, const float* __restrict__ W1,
                        const float* __restrict__ b1) {
    int e = blockIdx.x;
    int k = threadIdx.x;
    const float* row = ef + (size_t)e * DEI;
    float acc = b1[k];
#pragma unroll
    for (int i = 0; i < DEI; ++i)
        acc = fmaf(__ldg(&row[i]), __ldg(&W1[i * EH + k]), acc);
    g_A[(size_t)e * EH + k] = fmaxf(acc, 0.f);
}

// ---------------- edge MLP stage 2: EW = a @ W_e2 + b_e2 (fp32 FFMA2, fp16 store)
#define E2_SMEM_BYTES (128 * 132 * 4)
__global__ void __launch_bounds__(256) k_edge2(const float* __restrict__ W2,
                                               const float* __restrict__ b2) {
    extern __shared__ float AsT[];   // [k=128][edge pad 132]
    int tid = threadIdx.x;
    int tx = tid & 15;               // col group
    int ty = tid >> 4;               // edge group
    int e0 = blockIdx.x * 128;
    int c0 = blockIdx.y * 128;
    int cbase = c0 + tx * 8;

    for (int idx = tid; idx < 128 * 128; idx += 256) {
        int el = idx >> 7;
        int kk = idx & 127;
        int e = e0 + el;
        AsT[kk * 132 + el] = (e < NE) ? g_A[(size_t)e * EH + kk] : 0.f;
    }
    __syncthreads();

    unsigned long long acc[8][4];
#pragma unroll
    for (int j = 0; j < 8; ++j)
#pragma unroll
        for (int p = 0; p < 4; ++p) acc[j][p] = 0ull;

#pragma unroll 2
    for (int k = 0; k < 128; ++k) {
        const float* arow = &AsT[k * 132 + ty * 8];
        float4 a0 = *reinterpret_cast<const float4*>(arow);
        float4 a1 = *reinterpret_cast<const float4*>(arow + 4);
        unsigned long long ap[8];
        ap[0] = pack2(a0.x, a0.x); ap[1] = pack2(a0.y, a0.y);
        ap[2] = pack2(a0.z, a0.z); ap[3] = pack2(a0.w, a0.w);
        ap[4] = pack2(a1.x, a1.x); ap[5] = pack2(a1.y, a1.y);
        ap[6] = pack2(a1.z, a1.z); ap[7] = pack2(a1.w, a1.w);

        const float* wrow = W2 + ((size_t)k << 12) + cbase;
        ulonglong2 wA = *reinterpret_cast<const ulonglong2*>(wrow);
        ulonglong2 wB = *reinterpret_cast<const ulonglong2*>(wrow + 4);
#pragma unroll
        for (int j = 0; j < 8; ++j) {
            acc[j][0] = fma2(ap[j], wA.x, acc[j][0]);
            acc[j][1] = fma2(ap[j], wA.y, acc[j][1]);
            acc[j][2] = fma2(ap[j], wB.x, acc[j][2]);
            acc[j][3] = fma2(ap[j], wB.y, acc[j][3]);
        }
    }

    float4 bA = *reinterpret_cast<const float4*>(b2 + cbase);
    float4 bB = *reinterpret_cast<const float4*>(b2 + cbase + 4);
#pragma unroll
    for (int j = 0; j < 8; ++j) {
        int e = e0 + ty * 8 + j;
        if (e < NE) {
            float2 p0 = unpack2(acc[j][0]);
            float2 p1 = unpack2(acc[j][1]);
            float2 p2 = unpack2(acc[j][2]);
            float2 p3 = unpack2(acc[j][3]);
            __half2 h0 = __floats2half2_rn(p0.x + bA.x, p0.y + bA.y);
            __half2 h1 = __floats2half2_rn(p1.x + bA.z, p1.y + bA.w);
            __half2 h2 = __floats2half2_rn(p2.x + bB.x, p2.y + bB.y);
            __half2 h3 = __floats2half2_rn(p3.x + bB.z, p3.y + bB.w);
            uint4 st;
            st.x = *reinterpret_cast<unsigned*>(&h0);
            st.y = *reinterpret_cast<unsigned*>(&h1);
            st.z = *reinterpret_cast<unsigned*>(&h2);
            st.w = *reinterpret_cast<unsigned*>(&h3);
            *reinterpret_cast<uint4*>(g_EWh + (size_t)e * 4096 + cbase) = st;
        }
    }
}

// ---------------- per-step kernels ----------------
__global__ void k_zero_rst() {
    int i = blockIdx.x * blockDim.x + threadIdx.x;
    if (i < NN * DD) g_RST[i] = 0.f;
    if (i < DD) { g_colsum[i] = 0.f; g_colsq[i] = 0.f; }
}

// msg[e] = h[src[e]] @ EW[e] (fp16 EW, fp32 accum); scatter-add into RST[dst].
__global__ void __launch_bounds__(256) k_msg(const int* __restrict__ src,
                                             const int* __restrict__ dst) {
    __shared__ float hbuf[8][64];
    int w = threadIdx.x >> 5;
    int lane = threadIdx.x & 31;
    int e = blockIdx.x * 8 + w;
    if (e >= NE) return;
    int s = src[e];
    int d = dst[e];
    hbuf[w][lane]      = g_H[(size_t)s * DD + lane];
    hbuf[w][lane + 32] = g_H[(size_t)s * DD + 32 + lane];
    __syncwarp();

    int r = lane >> 3;     // row phase 0..3
    int c = lane & 7;      // col group of 8
    const uint4* M = reinterpret_cast<const uint4*>(g_EWh + (size_t)e * 4096) + c;
    float acc[8];
#pragma unroll
    for (int q = 0; q < 8; ++q) acc[q] = 0.f;

#pragma unroll
    for (int t = 0; t < 16; ++t) {
        int i = t * 4 + r;
        uint4 wv = M[i * 8];
        float hv = hbuf[w][i];
        const __half2* hp = reinterpret_cast<const __half2*>(&wv);
#pragma unroll
        for (int q = 0; q < 4; ++q) {
            float2 f = __half22float2(hp[q]);
            acc[2 * q]     = fmaf(hv, f.x, acc[2 * q]);
            acc[2 * q + 1] = fmaf(hv, f.y, acc[2 * q + 1]);
        }
    }
#pragma unroll
    for (int q = 0; q < 8; ++q) {
        acc[q] += __shfl_xor_sync(0xffffffffu, acc[q], 8);
        acc[q] += __shfl_xor_sync(0xffffffffu, acc[q], 16);
    }
    if (r == 0) {
        float* out = g_RST + (size_t)d * DD + c * 8;
#pragma unroll
        for (int q = 0; q < 8; ++q) atomicAdd(out + q, acc[q]);
    }
}

// rst = rst*invdeg + conv_bias (written back) + per-column sum/sumsq
__global__ void k_bnred(const float* __restrict__ cbias) {
    int o = threadIdx.x & 63;
    int ty = threadIdx.x >> 6;    // 0..3
    int v0 = blockIdx.x * 128;
    float cb = cbias[o];
    float s = 0.f, s2 = 0.f;
#pragma unroll 4
    for (int t = 0; t < 32; ++t) {
        int v = v0 + ty + t * 4;
        if (v < NN) {
            size_t idx = (size_t)v * DD + o;
            float x = fmaf(g_RST[idx], g_invdeg[v], cb);
            g_RST[idx] = x;
            s += x;
            s2 = fmaf(x, x, s2);
        }
    }
    __shared__ float ss[4][64], ss2[4][64];
    ss[ty][o] = s;
    ss2[ty][o] = s2;
    __syncthreads();
    if (ty == 0) {
        s  = ss[0][o] + ss[1][o] + ss[2][o] + ss[3][o];
        s2 = ss2[0][o] + ss2[1][o] + ss2[2][o] + ss2[3][o];
        atomicAdd(&g_colsum[o], s);
        atomicAdd(&g_colsq[o], s2);
    }
}

__global__ void k_bnfin(const float* __restrict__ gamma, const float* __restrict__ beta) {
    int o = threadIdx.x;
    const float invn = 1.f / (float)NN;
    float mu = g_colsum[o] * invn;
    float var = g_colsq[o] * invn - mu * mu;
    float sc = gamma[o] * rsqrtf(var + BN_EPS);
    g_bnscale[o] = sc;
    g_bnshift[o] = beta[o] - mu * sc;
}

// GRU cell for 64 nodes per block; W rows live in registers (FFMA2 pairs)
__global__ void __launch_bounds__(192) k_gru(const float* __restrict__ W_ih,
                                             const float* __restrict__ W_hh,
                                             const float* __restrict__ b_ih,
                                             const float* __restrict__ b_hh,
                                             float* __restrict__ out, int last) {
    __shared__ float m_s[64], h_s[64], gi_s[192], gh_s[192];
    int j = threadIdx.x;

    unsigned long long wih[32], whh[32];
    const unsigned long long* pih = reinterpret_cast<const unsigned long long*>(W_ih) + j * 32;
    const unsigned long long* phh = reinterpret_cast<const unsigned long long*>(W_hh) + j * 32;
#pragma unroll
    for (int q = 0; q < 32; ++q) { wih[q] = pih[q]; whh[q] = phh[q]; }
    float bi = b_ih[j], bh = b_hh[j];
    float sc = 0.f, sh = 0.f;
    if (j < 64) { sc = g_bnscale[j]; sh = g_bnshift[j]; }

    int v0 = blockIdx.x * 64;
    for (int n = 0; n < 64; ++n) {
        int v = v0 + n;
        if (v >= NN) break;                         // uniform across block
        if (j < 64) {
            float x = g_RST[(size_t)v * DD + j];
            m_s[j] = fmaxf(fmaf(x, sc, sh), 0.f);   // BN affine + ReLU
        } else if (j < 128) {
            h_s[j - 64] = g_H[(size_t)v * DD + (j - 64)];
        }
        __syncthreads();

        unsigned long long gi2 = 0ull, gh2 = 0ull;
        const unsigned long long* m2 = reinterpret_cast<const unsigned long long*>(m_s);
        const unsigned long long* h2 = reinterpret_cast<const unsigned long long*>(h_s);
#pragma unroll
        for (int q = 0; q < 32; ++q) {
            gi2 = fma2(m2[q], wih[q], gi2);
            gh2 = fma2(h2[q], whh[q], gh2);
        }
        float2 gi = unpack2(gi2);
        float2 gh = unpack2(gh2);
        gi_s[j] = gi.x + gi.y + bi;
        gh_s[j] = gh.x + gh.y + bh;
        __syncthreads();

        if (j < 64) {
            float r = 1.f / (1.f + expf(-(gi_s[j] + gh_s[j])));
            float z = 1.f / (1.f + expf(-(gi_s[64 + j] + gh_s[64 + j])));
            float nn = tanhf(gi_s[128 + j] + r * gh_s[128 + j]);
            float hnew = (1.f - z) * nn + z * h_s[j];
            g_H[(size_t)v * DD + j] = hnew;
            if (last) out[(size_t)v * DD + j] = hnew;
        }
        __syncthreads();
    }
}

// ---------------- launch ----------------
extern "C" void kernel_launch(void* const* d_in, const int* in_sizes, int n_in,
                              void* d_out, int out_size) {
    const float *node_feats = nullptr, *edge_feats = nullptr;
    const float *W_proj = nullptr, *b_proj = nullptr;
    const float *W_e1 = nullptr, *b_e1 = nullptr, *W_e2 = nullptr, *b_e2 = nullptr;
    const float *conv_bias = nullptr, *bn_gamma = nullptr, *bn_beta = nullptr;
    const float *W_ih = nullptr, *W_hh = nullptr, *b_ih = nullptr, *b_hh = nullptr;
    const int *src = nullptr, *dst = nullptr;
    int c60000 = 0, c64 = 0, c12288 = 0, c192 = 0;

    for (int i = 0; i < n_in; ++i) {
        const void* p = d_in[i];
        switch (in_sizes[i]) {
            case 1110000: node_feats = (const float*)p; break;
            case 720000:  edge_feats = (const float*)p; break;
            case 60000:   if (c60000++ == 0) src = (const int*)p; else dst = (const int*)p; break;
            case 4736:    W_proj = (const float*)p; break;
            case 64:
                if (c64 == 0) b_proj = (const float*)p;
                else if (c64 == 1) conv_bias = (const float*)p;
                else if (c64 == 2) bn_gamma = (const float*)p;
                else bn_beta = (const float*)p;
                ++c64; break;
            case 1536:    W_e1 = (const float*)p; break;
            case 128:     b_e1 = (const float*)p; break;
            case 524288:  W_e2 = (const float*)p; break;
            case 4096:    b_e2 = (const float*)p; break;
            case 12288:   if (c12288++ == 0) W_ih = (const float*)p; else W_hh = (const float*)p; break;
            case 192:     if (c192++ == 0) b_ih = (const float*)p; else b_hh = (const float*)p; break;
            default: break;
        }
    }
    if (!node_feats || !edge_feats || !src || !dst || !W_proj || !b_proj || !W_e1 ||
        !b_e1 || !W_e2 || !b_e2 || !conv_bias || !bn_gamma || !bn_beta || !W_ih ||
        !W_hh || !b_ih || !b_hh)
        return;

    cudaFuncSetAttribute(k_edge2, cudaFuncAttributeMaxDynamicSharedMemorySize, E2_SMEM_BYTES);

    // degree + inverse
    k_zero_deg<<<(NN + 255) / 256, 256>>>();
    k_deg<<<(NE + 255) / 256, 256>>>(dst);
    k_invdeg<<<(NN + 255) / 256, 256>>>();

    // static precompute
    k_proj<<<NN, DD>>>(node_feats, W_proj, b_proj);
    k_edge1<<<NE, EH>>>(edge_feats, W_e1, b_e1);
    k_edge2<<<dim3((NE + 127) / 128, 32), 256, E2_SMEM_BYTES>>>(W_e2, b_e2);

    // message-passing steps
    for (int s = 0; s < NSTEPS; ++s) {
        k_zero_rst<<<(NN * DD + 255) / 256, 256>>>();
        k_msg<<<(NE + 7) / 8, 256>>>(src, dst);
        k_bnred<<<(NN + 127) / 128, 256>>>(conv_bias);
        k_bnfin<<<1, 64>>>(bn_gamma, bn_beta);
        k_gru<<<(NN + 63) / 64, 192>>>(W_ih, W_hh, b_ih, b_hh,
                                       (float*)d_out, s == NSTEPS - 1);
    }
}

// round 4
// speedup vs baseline: 2.2254x; 1.8465x over previous
#include <cuda_runtime.h>
#include <cuda_fp16.h>
#include <cuda_bf16.h>
#include <math.h>

// ---------------- problem constants ----------------
#define NN      15000
#define NE      60000
#define DIN     74
#define DEI     12
#define DD      64
#define EH      128
#define NSTEPS  6
#define BN_EPS  1e-5f

// ---------------- scratch (device globals; allocation-free) ----------------
__device__ float  g_H[NN * DD];
__device__ __half g_Ah[NE * EH];                 // edge hidden a (fp16)
__device__ __half g_W2h[EH * DD * DD];           // W_e2 fp16 (1 MB, L2-resident)
__device__ __half g_EWh[(size_t)NE * DD * DD];   // per-edge matrices, fp16 (492 MB)
__device__ float  g_RST[NN * DD];
__device__ float  g_deg[NN];
__device__ float  g_invdeg[NN];
__device__ float  g_colsum[DD];
__device__ float  g_colsq[DD];
__device__ float  g_bnscale[DD];
__device__ float  g_bnshift[DD];

// ---------------- f32x2 packed-FMA helpers (Blackwell FFMA2) ----------------
__device__ __forceinline__ unsigned long long pack2(float x, float y) {
    unsigned long long r;
    asm("mov.b64 %0, {%1, %2};" : "=l"(r) : "f"(x), "f"(y));
    return r;
}
__device__ __forceinline__ unsigned long long fma2(unsigned long long a,
                                                   unsigned long long b,
                                                   unsigned long long c) {
    unsigned long long d;
    asm("fma.rn.f32x2 %0, %1, %2, %3;" : "=l"(d) : "l"(a), "l"(b), "l"(c));
    return d;
}
__device__ __forceinline__ float2 unpack2(unsigned long long v) {
    float2 f;
    asm("mov.b64 {%0, %1}, %2;" : "=f"(f.x), "=f"(f.y) : "l"(v));
    return f;
}

// ---------------- tensor-core helpers ----------------
__device__ __forceinline__ unsigned smem_u32(const void* p) {
    return (unsigned)__cvta_generic_to_shared(p);
}
__device__ __forceinline__ void ldmA(unsigned& a0, unsigned& a1, unsigned& a2,
                                     unsigned& a3, unsigned addr) {
    asm volatile("ldmatrix.sync.aligned.m8n8.x4.shared.b16 {%0,%1,%2,%3}, [%4];"
                 : "=r"(a0), "=r"(a1), "=r"(a2), "=r"(a3) : "r"(addr));
}
__device__ __forceinline__ void ldmBT(unsigned& b0, unsigned& b1, unsigned& b2,
                                      unsigned& b3, unsigned addr) {
    asm volatile("ldmatrix.sync.aligned.m8n8.x4.trans.shared.b16 {%0,%1,%2,%3}, [%4];"
                 : "=r"(b0), "=r"(b1), "=r"(b2), "=r"(b3) : "r"(addr));
}
__device__ __forceinline__ void mma16816(float& c0, float& c1, float& c2, float& c3,
                                         unsigned a0, unsigned a1, unsigned a2,
                                         unsigned a3, unsigned b0, unsigned b1) {
    asm volatile(
        "mma.sync.aligned.m16n8k16.row.col.f32.f16.f16.f32 "
        "{%0,%1,%2,%3}, {%4,%5,%6,%7}, {%8,%9}, {%0,%1,%2,%3};"
        : "+f"(c0), "+f"(c1), "+f"(c2), "+f"(c3)
        : "r"(a0), "r"(a1), "r"(a2), "r"(a3), "r"(b0), "r"(b1));
}

// ---------------- small kernels ----------------
__global__ void k_zero_deg() {
    int i = blockIdx.x * blockDim.x + threadIdx.x;
    if (i < NN) g_deg[i] = 0.f;
}

__global__ void k_deg(const int* __restrict__ dst) {
    int e = blockIdx.x * blockDim.x + threadIdx.x;
    if (e < NE) atomicAdd(&g_deg[dst[e]], 1.f);
}

__global__ void k_invdeg() {
    int i = blockIdx.x * blockDim.x + threadIdx.x;
    if (i < NN) {
        float d = g_deg[i];
        g_invdeg[i] = (d > 0.f) ? (1.f / d) : 0.f;
    }
}

__global__ void k_proj(const float* __restrict__ nf, const float* __restrict__ Wp,
                       const float* __restrict__ bp) {
    int r = blockIdx.x;
    int o = threadIdx.x;
    const float* row = nf + (size_t)r * DIN;
    float acc = bp[o];
#pragma unroll 2
    for (int i = 0; i < DIN; ++i)
        acc = fmaf(__ldg(&row[i]), __ldg(&Wp[i * DD + o]), acc);
    g_H[(size_t)r * DD + o] = fmaxf(acc, 0.f);
}

// a = relu(edge_feats @ W_e1 + b_e1) -> fp16
__global__ void k_edge1(const float* __restrict__ ef, const float* __restrict__ W1,
                        const float* __restrict__ b1) {
    int e = blockIdx.x;
    int k = threadIdx.x;
    const float* row = ef + (size_t)e * DEI;
    float acc = b1[k];
#pragma unroll
    for (int i = 0; i < DEI; ++i)
        acc = fmaf(__ldg(&row[i]), __ldg(&W1[i * EH + k]), acc);
    g_Ah[(size_t)e * EH + k] = __float2half_rn(fmaxf(acc, 0.f));
}

__global__ void k_w2cvt(const float* __restrict__ W2) {
    int i = blockIdx.x * blockDim.x + threadIdx.x;
    if (i < EH * DD * DD) g_W2h[i] = __float2half_rn(W2[i]);
}

// ---------------- edge MLP stage 2 on tensor cores --------------------------
// EW[64 edges x 64 cols per block] = A[64x128] @ W2h[128x(n0..n0+64)] + b2
__global__ void __launch_bounds__(128) k_edge2t(const float* __restrict__ b2) {
    __shared__ __half As[64][136];    // pad 8 halves: 272B row stride (odd 16B units)
    __shared__ __half Bs[128][72];    // pad 8 halves: 144B row stride

    int tid  = threadIdx.x;
    int warp = tid >> 5;
    int lane = tid & 31;
    int e0 = blockIdx.x * 64;
    int n0 = blockIdx.y * 64;

    // stage A (64 rows x 128 halves) : 1024 x 8-half chunks
    for (int i = tid; i < 64 * 16; i += 128) {
        int row = i >> 4, seg = i & 15;
        int e = e0 + row;
        uint4 v = (e < NE)
            ? *reinterpret_cast<const uint4*>(&g_Ah[(size_t)e * EH + seg * 8])
            : make_uint4(0u, 0u, 0u, 0u);
        *reinterpret_cast<uint4*>(&As[row][seg * 8]) = v;
    }
    // stage B (128 rows x 64 halves)
    for (int i = tid; i < 128 * 8; i += 128) {
        int row = i >> 3, seg = i & 7;
        uint4 v = *reinterpret_cast<const uint4*>(&g_W2h[(size_t)row * 4096 + n0 + seg * 8]);
        *reinterpret_cast<uint4*>(&Bs[row][seg * 8]) = v;
    }
    __syncthreads();

    float acc[8][4];
#pragma unroll
    for (int t = 0; t < 8; ++t)
#pragma unroll
        for (int p = 0; p < 4; ++p) acc[t][p] = 0.f;

    unsigned aBase = smem_u32(&As[warp * 16 + (lane & 15)][(lane >> 4) * 8]);
    unsigned bBase = smem_u32(&Bs[lane & 15][(lane >> 4) * 8]);

#pragma unroll
    for (int ks = 0; ks < 8; ++ks) {
        unsigned a0, a1, a2, a3;
        ldmA(a0, a1, a2, a3, aBase + ks * 32);      // +16 halves per k-step
#pragma unroll
        for (int nt = 0; nt < 4; ++nt) {
            unsigned b0, b1, b2v, b3;
            ldmBT(b0, b1, b2v, b3, bBase + ks * 16 * 144 + nt * 32);
            mma16816(acc[2 * nt][0], acc[2 * nt][1], acc[2 * nt][2], acc[2 * nt][3],
                     a0, a1, a2, a3, b0, b1);
            mma16816(acc[2 * nt + 1][0], acc[2 * nt + 1][1], acc[2 * nt + 1][2],
                     acc[2 * nt + 1][3], a0, a1, a2, a3, b2v, b3);
        }
    }

    // epilogue: + bias, fp16 store
    int r0 = e0 + warp * 16 + (lane >> 2);
    int cb = (lane & 3) * 2;
#pragma unroll
    for (int t = 0; t < 8; ++t) {
        int col = n0 + t * 8 + cb;
        float bx = __ldg(&b2[col]);
        float by = __ldg(&b2[col + 1]);
        if (r0 < NE) {
            __half2 h = __floats2half2_rn(acc[t][0] + bx, acc[t][1] + by);
            *reinterpret_cast<__half2*>(&g_EWh[(size_t)r0 * 4096 + col]) = h;
        }
        if (r0 + 8 < NE) {
            __half2 h = __floats2half2_rn(acc[t][2] + bx, acc[t][3] + by);
            *reinterpret_cast<__half2*>(&g_EWh[(size_t)(r0 + 8) * 4096 + col]) = h;
        }
    }
}

// ---------------- per-step kernels ----------------
__global__ void k_zero_rst() {
    int i = blockIdx.x * blockDim.x + threadIdx.x;
    if (i < NN * DD) g_RST[i] = 0.f;
    if (i < DD) { g_colsum[i] = 0.f; g_colsq[i] = 0.f; }
}

// msg[e] = h[src[e]] @ EW[e] (fp16 EW, fp32 accum); scatter-add into RST[dst].
__global__ void __launch_bounds__(256) k_msg(const int* __restrict__ src,
                                             const int* __restrict__ dst) {
    __shared__ float hbuf[8][64];
    int w = threadIdx.x >> 5;
    int lane = threadIdx.x & 31;
    int e = blockIdx.x * 8 + w;
    if (e >= NE) return;
    int s = src[e];
    int d = dst[e];
    hbuf[w][lane]      = g_H[(size_t)s * DD + lane];
    hbuf[w][lane + 32] = g_H[(size_t)s * DD + 32 + lane];
    __syncwarp();

    int r = lane >> 3;
    int c = lane & 7;
    const uint4* M = reinterpret_cast<const uint4*>(g_EWh + (size_t)e * 4096) + c;
    float acc[8];
#pragma unroll
    for (int q = 0; q < 8; ++q) acc[q] = 0.f;

#pragma unroll
    for (int t = 0; t < 16; ++t) {
        int i = t * 4 + r;
        uint4 wv = M[i * 8];
        float hv = hbuf[w][i];
        const __half2* hp = reinterpret_cast<const __half2*>(&wv);
#pragma unroll
        for (int q = 0; q < 4; ++q) {
            float2 f = __half22float2(hp[q]);
            acc[2 * q]     = fmaf(hv, f.x, acc[2 * q]);
            acc[2 * q + 1] = fmaf(hv, f.y, acc[2 * q + 1]);
        }
    }
#pragma unroll
    for (int q = 0; q < 8; ++q) {
        acc[q] += __shfl_xor_sync(0xffffffffu, acc[q], 8);
        acc[q] += __shfl_xor_sync(0xffffffffu, acc[q], 16);
    }
    if (r == 0) {
        float* out = g_RST + (size_t)d * DD + c * 8;
#pragma unroll
        for (int q = 0; q < 8; ++q) atomicAdd(out + q, acc[q]);
    }
}

__global__ void k_bnred(const float* __restrict__ cbias) {
    int o = threadIdx.x & 63;
    int ty = threadIdx.x >> 6;
    int v0 = blockIdx.x * 128;
    float cb = cbias[o];
    float s = 0.f, s2 = 0.f;
#pragma unroll 4
    for (int t = 0; t < 32; ++t) {
        int v = v0 + ty + t * 4;
        if (v < NN) {
            size_t idx = (size_t)v * DD + o;
            float x = fmaf(g_RST[idx], g_invdeg[v], cb);
            g_RST[idx] = x;
            s += x;
            s2 = fmaf(x, x, s2);
        }
    }
    __shared__ float ss[4][64], ss2[4][64];
    ss[ty][o] = s;
    ss2[ty][o] = s2;
    __syncthreads();
    if (ty == 0) {
        s  = ss[0][o] + ss[1][o] + ss[2][o] + ss[3][o];
        s2 = ss2[0][o] + ss2[1][o] + ss2[2][o] + ss2[3][o];
        atomicAdd(&g_colsum[o], s);
        atomicAdd(&g_colsq[o], s2);
    }
}

// computes BN scale/shift, then resets colsum/colsq for the next step
__global__ void k_bnfin(const float* __restrict__ gamma, const float* __restrict__ beta) {
    int o = threadIdx.x;
    const float invn = 1.f / (float)NN;
    float mu = g_colsum[o] * invn;
    float var = g_colsq[o] * invn - mu * mu;
    float sc = gamma[o] * rsqrtf(var + BN_EPS);
    g_bnscale[o] = sc;
    g_bnshift[o] = beta[o] - mu * sc;
    g_colsum[o] = 0.f;
    g_colsq[o] = 0.f;
}

// GRU; also zeroes RST after consuming (ready for next step's atomics)
__global__ void __launch_bounds__(192) k_gru(const float* __restrict__ W_ih,
                                             const float* __restrict__ W_hh,
                                             const float* __restrict__ b_ih,
                                             const float* __restrict__ b_hh,
                                             float* __restrict__ out, int last) {
    __shared__ float m_s[64], h_s[64], gi_s[192], gh_s[192];
    int j = threadIdx.x;

    unsigned long long wih[32], whh[32];
    const unsigned long long* pih = reinterpret_cast<const unsigned long long*>(W_ih) + j * 32;
    const unsigned long long* phh = reinterpret_cast<const unsigned long long*>(W_hh) + j * 32;
#pragma unroll
    for (int q = 0; q < 32; ++q) { wih[q] = pih[q]; whh[q] = phh[q]; }
    float bi = b_ih[j], bh = b_hh[j];
    float sc = 0.f, sh = 0.f;
    if (j < 64) { sc = g_bnscale[j]; sh = g_bnshift[j]; }

    int v0 = blockIdx.x * 64;
    for (int n = 0; n < 64; ++n) {
        int v = v0 + n;
        if (v >= NN) break;
        if (j < 64) {
            float x = g_RST[(size_t)v * DD + j];
            g_RST[(size_t)v * DD + j] = 0.f;        // pre-zero for next step
            m_s[j] = fmaxf(fmaf(x, sc, sh), 0.f);
        } else if (j < 128) {
            h_s[j - 64] = g_H[(size_t)v * DD + (j - 64)];
        }
        __syncthreads();

        unsigned long long gi2 = 0ull, gh2 = 0ull;
        const unsigned long long* m2 = reinterpret_cast<const unsigned long long*>(m_s);
        const unsigned long long* h2 = reinterpret_cast<const unsigned long long*>(h_s);
#pragma unroll
        for (int q = 0; q < 32; ++q) {
            gi2 = fma2(m2[q], wih[q], gi2);
            gh2 = fma2(h2[q], whh[q], gh2);
        }
        float2 gi = unpack2(gi2);
        float2 gh = unpack2(gh2);
        gi_s[j] = gi.x + gi.y + bi;
        gh_s[j] = gh.x + gh.y + bh;
        __syncthreads();

        if (j < 64) {
            float r = 1.f / (1.f + expf(-(gi_s[j] + gh_s[j])));
            float z = 1.f / (1.f + expf(-(gi_s[64 + j] + gh_s[64 + j])));
            float nn = tanhf(gi_s[128 + j] + r * gh_s[128 + j]);
            float hnew = (1.f - z) * nn + z * h_s[j];
            g_H[(size_t)v * DD + j] = hnew;
            if (last) out[(size_t)v * DD + j] = hnew;
        }
        __syncthreads();
    }
}

// ---------------- launch ----------------
extern "C" void kernel_launch(void* const* d_in, const int* in_sizes, int n_in,
                              void* d_out, int out_size) {
    const float *node_feats = nullptr, *edge_feats = nullptr;
    const float *W_proj = nullptr, *b_proj = nullptr;
    const float *W_e1 = nullptr, *b_e1 = nullptr, *W_e2 = nullptr, *b_e2 = nullptr;
    const float *conv_bias = nullptr, *bn_gamma = nullptr, *bn_beta = nullptr;
    const float *W_ih = nullptr, *W_hh = nullptr, *b_ih = nullptr, *b_hh = nullptr;
    const int *src = nullptr, *dst = nullptr;
    int c60000 = 0, c64 = 0, c12288 = 0, c192 = 0;

    for (int i = 0; i < n_in; ++i) {
        const void* p = d_in[i];
        switch (in_sizes[i]) {
            case 1110000: node_feats = (const float*)p; break;
            case 720000:  edge_feats = (const float*)p; break;
            case 60000:   if (c60000++ == 0) src = (const int*)p; else dst = (const int*)p; break;
            case 4736:    W_proj = (const float*)p; break;
            case 64:
                if (c64 == 0) b_proj = (const float*)p;
                else if (c64 == 1) conv_bias = (const float*)p;
                else if (c64 == 2) bn_gamma = (const float*)p;
                else bn_beta = (const float*)p;
                ++c64; break;
            case 1536:    W_e1 = (const float*)p; break;
            case 128:     b_e1 = (const float*)p; break;
            case 524288:  W_e2 = (const float*)p; break;
            case 4096:    b_e2 = (const float*)p; break;
            case 12288:   if (c12288++ == 0) W_ih = (const float*)p; else W_hh = (const float*)p; break;
            case 192:     if (c192++ == 0) b_ih = (const float*)p; else b_hh = (const float*)p; break;
            default: break;
        }
    }
    if (!node_feats || !edge_feats || !src || !dst || !W_proj || !b_proj || !W_e1 ||
        !b_e1 || !W_e2 || !b_e2 || !conv_bias || !bn_gamma || !bn_beta || !W_ih ||
        !W_hh || !b_ih || !b_hh)
        return;

    // degree + inverse
    k_zero_deg<<<(NN + 255) / 256, 256>>>();
    k_deg<<<(NE + 255) / 256, 256>>>(dst);
    k_invdeg<<<(NN + 255) / 256, 256>>>();

    // static precompute
    k_proj<<<NN, DD>>>(node_feats, W_proj, b_proj);
    k_edge1<<<NE, EH>>>(edge_feats, W_e1, b_e1);
    k_w2cvt<<<(EH * DD * DD + 255) / 256, 256>>>(W_e2);
    k_edge2t<<<dim3((NE + 63) / 64, DD * DD / 64), 128>>>(b_e2);

    k_zero_rst<<<(NN * DD + 255) / 256, 256>>>();

    // message-passing steps
    for (int s = 0; s < NSTEPS; ++s) {
        k_msg<<<(NE + 7) / 8, 256>>>(src, dst);
        k_bnred<<<(NN + 127) / 128, 256>>>(conv_bias);
        k_bnfin<<<1, 64>>>(bn_gamma, bn_beta);
        k_gru<<<(NN + 63) / 64, 192>>>(W_ih, W_hh, b_ih, b_hh,
                                       (float*)d_out, s == NSTEPS - 1);
    }
}

// round 5
// speedup vs baseline: 2.4312x; 1.0925x over previous
#include <cuda_runtime.h>
#include <cuda_fp16.h>
#include <cuda_bf16.h>
#include <math.h>

// ---------------- problem constants ----------------
#define NN      15000
#define NE      60000
#define DIN     74
#define DEI     12
#define DD      64
#define EH      128
#define NSTEPS  6
#define BN_EPS  1e-5f

// ---------------- scratch (device globals; allocation-free) ----------------
__device__ float  g_H[NN * DD];
__device__ __half g_Ah[NE * EH];                 // edge hidden a (fp16)
__device__ __half g_W2h[EH * DD * DD];           // W_e2 fp16 (1 MB, L2-resident)
__device__ __half g_EWh[(size_t)NE * DD * DD];   // per-edge matrices, fp16 (492 MB)
__device__ float  g_RST[NN * DD];
__device__ float  g_deg[NN];
__device__ float  g_invdeg[NN];
__device__ float  g_colsum[DD];
__device__ float  g_colsq[DD];
__device__ float  g_bnscale[DD];
__device__ float  g_bnshift[DD];
__device__ unsigned g_bnctr;

// ---------------- f32x2 packed-FMA helpers (Blackwell FFMA2) ----------------
__device__ __forceinline__ unsigned long long fma2(unsigned long long a,
                                                   unsigned long long b,
                                                   unsigned long long c) {
    unsigned long long d;
    asm("fma.rn.f32x2 %0, %1, %2, %3;" : "=l"(d) : "l"(a), "l"(b), "l"(c));
    return d;
}
__device__ __forceinline__ float2 unpack2(unsigned long long v) {
    float2 f;
    asm("mov.b64 {%0, %1}, %2;" : "=f"(f.x), "=f"(f.y) : "l"(v));
    return f;
}

// ---------------- tensor-core helpers ----------------
__device__ __forceinline__ unsigned smem_u32(const void* p) {
    return (unsigned)__cvta_generic_to_shared(p);
}
__device__ __forceinline__ void ldmA(unsigned& a0, unsigned& a1, unsigned& a2,
                                     unsigned& a3, unsigned addr) {
    asm volatile("ldmatrix.sync.aligned.m8n8.x4.shared.b16 {%0,%1,%2,%3}, [%4];"
                 : "=r"(a0), "=r"(a1), "=r"(a2), "=r"(a3) : "r"(addr));
}
__device__ __forceinline__ void ldmBT(unsigned& b0, unsigned& b1, unsigned& b2,
                                      unsigned& b3, unsigned addr) {
    asm volatile("ldmatrix.sync.aligned.m8n8.x4.trans.shared.b16 {%0,%1,%2,%3}, [%4];"
                 : "=r"(b0), "=r"(b1), "=r"(b2), "=r"(b3) : "r"(addr));
}
__device__ __forceinline__ void mma16816(float& c0, float& c1, float& c2, float& c3,
                                         unsigned a0, unsigned a1, unsigned a2,
                                         unsigned a3, unsigned b0, unsigned b1) {
    asm volatile(
        "mma.sync.aligned.m16n8k16.row.col.f32.f16.f16.f32 "
        "{%0,%1,%2,%3}, {%4,%5,%6,%7}, {%8,%9}, {%0,%1,%2,%3};"
        : "+f"(c0), "+f"(c1), "+f"(c2), "+f"(c3)
        : "r"(a0), "r"(a1), "r"(a2), "r"(a3), "r"(b0), "r"(b1));
}

// ---------------- small kernels ----------------
__global__ void k_zero_deg() {
    int i = blockIdx.x * blockDim.x + threadIdx.x;
    if (i < NN) g_deg[i] = 0.f;
}

__global__ void k_deg(const int* __restrict__ dst) {
    int e = blockIdx.x * blockDim.x + threadIdx.x;
    if (e < NE) atomicAdd(&g_deg[dst[e]], 1.f);
}

__global__ void k_invdeg() {
    int i = blockIdx.x * blockDim.x + threadIdx.x;
    if (i < NN) {
        float d = g_deg[i];
        g_invdeg[i] = (d > 0.f) ? (1.f / d) : 0.f;
    }
}

__global__ void k_proj(const float* __restrict__ nf, const float* __restrict__ Wp,
                       const float* __restrict__ bp) {
    int r = blockIdx.x;
    int o = threadIdx.x;
    const float* row = nf + (size_t)r * DIN;
    float acc = bp[o];
#pragma unroll 2
    for (int i = 0; i < DIN; ++i)
        acc = fmaf(__ldg(&row[i]), __ldg(&Wp[i * DD + o]), acc);
    g_H[(size_t)r * DD + o] = fmaxf(acc, 0.f);
}

// a = relu(edge_feats @ W_e1 + b_e1) -> fp16
__global__ void k_edge1(const float* __restrict__ ef, const float* __restrict__ W1,
                        const float* __restrict__ b1) {
    int e = blockIdx.x;
    int k = threadIdx.x;
    const float* row = ef + (size_t)e * DEI;
    float acc = b1[k];
#pragma unroll
    for (int i = 0; i < DEI; ++i)
        acc = fmaf(__ldg(&row[i]), __ldg(&W1[i * EH + k]), acc);
    g_Ah[(size_t)e * EH + k] = __float2half_rn(fmaxf(acc, 0.f));
}

__global__ void k_w2cvt(const float* __restrict__ W2) {
    int i = blockIdx.x * blockDim.x + threadIdx.x;
    if (i < EH * DD * DD) g_W2h[i] = __float2half_rn(W2[i]);
}

// ---------------- edge MLP stage 2 on tensor cores --------------------------
// Block: 128 edges; loops all 64 column tiles. A in smem once (A frags hoisted
// to registers), B tiles double-buffered via cp.async.
#define E2_AS_BYTES   (128 * 136 * 2)          // 34816
#define E2_BS_BYTES   (128 * 72 * 2)           // 18432
#define E2_SMEM_TOTAL (E2_AS_BYTES + 2 * E2_BS_BYTES)

__global__ void __launch_bounds__(256) k_edge2t(const float* __restrict__ b2) {
    extern __shared__ char sm[];
    __half (*As)[136] = reinterpret_cast<__half(*)[136]>(sm);
    __half* BsBuf[2] = { reinterpret_cast<__half*>(sm + E2_AS_BYTES),
                         reinterpret_cast<__half*>(sm + E2_AS_BYTES + E2_BS_BYTES) };

    int tid  = threadIdx.x;
    int warp = tid >> 5;
    int lane = tid & 31;
    int e0 = blockIdx.x * 128;

    // stage A (128 edges x 128 halves)
    for (int i = tid; i < 128 * 16; i += 256) {
        int row = i >> 4, seg = i & 15;
        int e = e0 + row;
        uint4 v = (e < NE)
            ? *reinterpret_cast<const uint4*>(&g_Ah[(size_t)e * EH + seg * 8])
            : make_uint4(0u, 0u, 0u, 0u);
        *reinterpret_cast<uint4*>(&As[row][seg * 8]) = v;
    }

    // prefetch first B tile (128 x 64 halves) via cp.async
    {
        for (int i = tid; i < 128 * 8; i += 256) {
            int row = i >> 3, seg = i & 7;
            const __half* src = &g_W2h[(size_t)row * 4096 + seg * 8];
            unsigned da = smem_u32(BsBuf[0] + row * 72 + seg * 8);
            asm volatile("cp.async.cg.shared.global [%0], [%1], 16;" :: "r"(da), "l"(src));
        }
        asm volatile("cp.async.commit_group;");
    }
    __syncthreads();

    // hoist A fragments for all 8 k-steps
    unsigned aBase = smem_u32(&As[warp * 16 + (lane & 15)][(lane >> 4) * 8]);
    unsigned afr[8][4];
#pragma unroll
    for (int ks = 0; ks < 8; ++ks)
        ldmA(afr[ks][0], afr[ks][1], afr[ks][2], afr[ks][3], aBase + ks * 32);

    unsigned bBaseOff = (lane & 15) * 144 + (lane >> 4) * 16;   // bytes within tile
    int r0 = e0 + warp * 16 + (lane >> 2);
    int cb = (lane & 3) * 2;

    for (int ntile = 0; ntile < 64; ++ntile) {
        int buf = ntile & 1;
        if (ntile + 1 < 64) {
            int n1 = (ntile + 1) * 64;
            for (int i = tid; i < 128 * 8; i += 256) {
                int row = i >> 3, seg = i & 7;
                const __half* src = &g_W2h[(size_t)row * 4096 + n1 + seg * 8];
                unsigned da = smem_u32(BsBuf[buf ^ 1] + row * 72 + seg * 8);
                asm volatile("cp.async.cg.shared.global [%0], [%1], 16;" :: "r"(da), "l"(src));
            }
            asm volatile("cp.async.commit_group;");
            asm volatile("cp.async.wait_group 1;");
        } else {
            asm volatile("cp.async.wait_group 0;");
        }
        __syncthreads();

        float acc[8][4];
#pragma unroll
        for (int t = 0; t < 8; ++t)
#pragma unroll
            for (int p = 0; p < 4; ++p) acc[t][p] = 0.f;

        unsigned bBase = smem_u32(BsBuf[buf]) + bBaseOff;
#pragma unroll
        for (int ks = 0; ks < 8; ++ks) {
#pragma unroll
            for (int nt = 0; nt < 4; ++nt) {
                unsigned b0, b1, b2v, b3;
                ldmBT(b0, b1, b2v, b3, bBase + ks * 16 * 144 + nt * 32);
                mma16816(acc[2 * nt][0], acc[2 * nt][1], acc[2 * nt][2], acc[2 * nt][3],
                         afr[ks][0], afr[ks][1], afr[ks][2], afr[ks][3], b0, b1);
                mma16816(acc[2 * nt + 1][0], acc[2 * nt + 1][1], acc[2 * nt + 1][2],
                         acc[2 * nt + 1][3],
                         afr[ks][0], afr[ks][1], afr[ks][2], afr[ks][3], b2v, b3);
            }
        }

        int n0 = ntile * 64;
#pragma unroll
        for (int t = 0; t < 8; ++t) {
            int col = n0 + t * 8 + cb;
            float bx = __ldg(&b2[col]);
            float by = __ldg(&b2[col + 1]);
            if (r0 < NE) {
                __half2 h = __floats2half2_rn(acc[t][0] + bx, acc[t][1] + by);
                *reinterpret_cast<__half2*>(&g_EWh[(size_t)r0 * 4096 + col]) = h;
            }
            if (r0 + 8 < NE) {
                __half2 h = __floats2half2_rn(acc[t][2] + bx, acc[t][3] + by);
                *reinterpret_cast<__half2*>(&g_EWh[(size_t)(r0 + 8) * 4096 + col]) = h;
            }
        }
        __syncthreads();   // protect BsBuf[buf^1] before next prefetch overwrite
    }
}

// ---------------- per-step kernels ----------------
__global__ void k_zero_rst() {
    int i = blockIdx.x * blockDim.x + threadIdx.x;
    if (i < NN * DD) g_RST[i] = 0.f;
    if (i < DD) { g_colsum[i] = 0.f; g_colsq[i] = 0.f; }
    if (i == 0) g_bnctr = 0u;
}

// msg[e] = h[src[e]] @ EW[e] (fp16 EW, fp32 accum); scatter-add into RST[dst].
__global__ void __launch_bounds__(256) k_msg(const int* __restrict__ src,
                                             const int* __restrict__ dst) {
    __shared__ float hbuf[8][64];
    int w = threadIdx.x >> 5;
    int lane = threadIdx.x & 31;
    int e = blockIdx.x * 8 + w;
    if (e >= NE) return;
    int s = src[e];
    int d = dst[e];
    hbuf[w][lane]      = g_H[(size_t)s * DD + lane];
    hbuf[w][lane + 32] = g_H[(size_t)s * DD + 32 + lane];
    __syncwarp();

    int r = lane >> 3;
    int c = lane & 7;
    const uint4* M = reinterpret_cast<const uint4*>(g_EWh + (size_t)e * 4096) + c;
    float acc[8];
#pragma unroll
    for (int q = 0; q < 8; ++q) acc[q] = 0.f;

#pragma unroll
    for (int t = 0; t < 16; ++t) {
        int i = t * 4 + r;
        uint4 wv = __ldcs(&M[i * 8]);        // streaming: zero reuse
        float hv = hbuf[w][i];
        const __half2* hp = reinterpret_cast<const __half2*>(&wv);
#pragma unroll
        for (int q = 0; q < 4; ++q) {
            float2 f = __half22float2(hp[q]);
            acc[2 * q]     = fmaf(hv, f.x, acc[2 * q]);
            acc[2 * q + 1] = fmaf(hv, f.y, acc[2 * q + 1]);
        }
    }
#pragma unroll
    for (int q = 0; q < 8; ++q) {
        acc[q] += __shfl_xor_sync(0xffffffffu, acc[q], 8);
        acc[q] += __shfl_xor_sync(0xffffffffu, acc[q], 16);
    }
    if (r == 0) {
        float* out = g_RST + (size_t)d * DD + c * 8;
#pragma unroll
        for (int q = 0; q < 8; ++q) atomicAdd(out + q, acc[q]);
    }
}

// rst = rst*invdeg + conv_bias, column sums; LAST block finalizes BN params
__global__ void k_bnred(const float* __restrict__ cbias,
                        const float* __restrict__ gamma,
                        const float* __restrict__ beta) {
    int o = threadIdx.x & 63;
    int ty = threadIdx.x >> 6;
    int v0 = blockIdx.x * 128;
    float cb = cbias[o];
    float s = 0.f, s2 = 0.f;
#pragma unroll 4
    for (int t = 0; t < 32; ++t) {
        int v = v0 + ty + t * 4;
        if (v < NN) {
            size_t idx = (size_t)v * DD + o;
            float x = fmaf(g_RST[idx], g_invdeg[v], cb);
            g_RST[idx] = x;
            s += x;
            s2 = fmaf(x, x, s2);
        }
    }
    __shared__ float ss[4][64], ss2[4][64];
    __shared__ int s_last;
    ss[ty][o] = s;
    ss2[ty][o] = s2;
    __syncthreads();
    if (ty == 0) {
        s  = ss[0][o] + ss[1][o] + ss[2][o] + ss[3][o];
        s2 = ss2[0][o] + ss2[1][o] + ss2[2][o] + ss2[3][o];
        atomicAdd(&g_colsum[o], s);
        atomicAdd(&g_colsq[o], s2);
    }
    __syncthreads();
    if (threadIdx.x == 0) {
        __threadfence();
        unsigned t = atomicAdd(&g_bnctr, 1u);
        s_last = (t == gridDim.x - 1);
    }
    __syncthreads();
    if (s_last) {
        __threadfence();                       // acquire side
        if (threadIdx.x < 64) {
            const float invn = 1.f / (float)NN;
            float mu = g_colsum[threadIdx.x] * invn;
            float var = g_colsq[threadIdx.x] * invn - mu * mu;
            float sc = gamma[threadIdx.x] * rsqrtf(var + BN_EPS);
            g_bnscale[threadIdx.x] = sc;
            g_bnshift[threadIdx.x] = beta[threadIdx.x] - mu * sc;
            g_colsum[threadIdx.x] = 0.f;
            g_colsq[threadIdx.x] = 0.f;
        }
        if (threadIdx.x == 0) g_bnctr = 0u;
    }
}

// GRU; zeroes RST after consuming (ready for next step's atomics)
__global__ void __launch_bounds__(192) k_gru(const float* __restrict__ W_ih,
                                             const float* __restrict__ W_hh,
                                             const float* __restrict__ b_ih,
                                             const float* __restrict__ b_hh,
                                             float* __restrict__ out, int last) {
    __shared__ float m_s[64], h_s[64], gi_s[192], gh_s[192];
    int j = threadIdx.x;

    unsigned long long wih[32], whh[32];
    const unsigned long long* pih = reinterpret_cast<const unsigned long long*>(W_ih) + j * 32;
    const unsigned long long* phh = reinterpret_cast<const unsigned long long*>(W_hh) + j * 32;
#pragma unroll
    for (int q = 0; q < 32; ++q) { wih[q] = pih[q]; whh[q] = phh[q]; }
    float bi = b_ih[j], bh = b_hh[j];
    float sc = 0.f, sh = 0.f;
    if (j < 64) { sc = g_bnscale[j]; sh = g_bnshift[j]; }

    int v0 = blockIdx.x * 64;
    for (int n = 0; n < 64; ++n) {
        int v = v0 + n;
        if (v >= NN) break;
        if (j < 64) {
            float x = g_RST[(size_t)v * DD + j];
            g_RST[(size_t)v * DD + j] = 0.f;
            m_s[j] = fmaxf(fmaf(x, sc, sh), 0.f);
        } else if (j < 128) {
            h_s[j - 64] = g_H[(size_t)v * DD + (j - 64)];
        }
        __syncthreads();

        unsigned long long gi2 = 0ull, gh2 = 0ull;
        const unsigned long long* m2 = reinterpret_cast<const unsigned long long*>(m_s);
        const unsigned long long* h2 = reinterpret_cast<const unsigned long long*>(h_s);
#pragma unroll
        for (int q = 0; q < 32; ++q) {
            gi2 = fma2(m2[q], wih[q], gi2);
            gh2 = fma2(h2[q], whh[q], gh2);
        }
        float2 gi = unpack2(gi2);
        float2 gh = unpack2(gh2);
        gi_s[j] = gi.x + gi.y + bi;
        gh_s[j] = gh.x + gh.y + bh;
        __syncthreads();

        if (j < 64) {
            float r = 1.f / (1.f + expf(-(gi_s[j] + gh_s[j])));
            float z = 1.f / (1.f + expf(-(gi_s[64 + j] + gh_s[64 + j])));
            float nn = tanhf(gi_s[128 + j] + r * gh_s[128 + j]);
            float hnew = (1.f - z) * nn + z * h_s[j];
            g_H[(size_t)v * DD + j] = hnew;
            if (last) out[(size_t)v * DD + j] = hnew;
        }
        __syncthreads();
    }
}

// ---------------- launch ----------------
extern "C" void kernel_launch(void* const* d_in, const int* in_sizes, int n_in,
                              void* d_out, int out_size) {
    const float *node_feats = nullptr, *edge_feats = nullptr;
    const float *W_proj = nullptr, *b_proj = nullptr;
    const float *W_e1 = nullptr, *b_e1 = nullptr, *W_e2 = nullptr, *b_e2 = nullptr;
    const float *conv_bias = nullptr, *bn_gamma = nullptr, *bn_beta = nullptr;
    const float *W_ih = nullptr, *W_hh = nullptr, *b_ih = nullptr, *b_hh = nullptr;
    const int *src = nullptr, *dst = nullptr;
    int c60000 = 0, c64 = 0, c12288 = 0, c192 = 0;

    for (int i = 0; i < n_in; ++i) {
        const void* p = d_in[i];
        switch (in_sizes[i]) {
            case 1110000: node_feats = (const float*)p; break;
            case 720000:  edge_feats = (const float*)p; break;
            case 60000:   if (c60000++ == 0) src = (const int*)p; else dst = (const int*)p; break;
            case 4736:    W_proj = (const float*)p; break;
            case 64:
                if (c64 == 0) b_proj = (const float*)p;
                else if (c64 == 1) conv_bias = (const float*)p;
                else if (c64 == 2) bn_gamma = (const float*)p;
                else bn_beta = (const float*)p;
                ++c64; break;
            case 1536:    W_e1 = (const float*)p; break;
            case 128:     b_e1 = (const float*)p; break;
            case 524288:  W_e2 = (const float*)p; break;
            case 4096:    b_e2 = (const float*)p; break;
            case 12288:   if (c12288++ == 0) W_ih = (const float*)p; else W_hh = (const float*)p; break;
            case 192:     if (c192++ == 0) b_ih = (const float*)p; else b_hh = (const float*)p; break;
            default: break;
        }
    }
    if (!node_feats || !edge_feats || !src || !dst || !W_proj || !b_proj || !W_e1 ||
        !b_e1 || !W_e2 || !b_e2 || !conv_bias || !bn_gamma || !bn_beta || !W_ih ||
        !W_hh || !b_ih || !b_hh)
        return;

    cudaFuncSetAttribute(k_edge2t, cudaFuncAttributeMaxDynamicSharedMemorySize,
                         E2_SMEM_TOTAL);

    // degree + inverse
    k_zero_deg<<<(NN + 255) / 256, 256>>>();
    k_deg<<<(NE + 255) / 256, 256>>>(dst);
    k_invdeg<<<(NN + 255) / 256, 256>>>();

    // static precompute
    k_proj<<<NN, DD>>>(node_feats, W_proj, b_proj);
    k_edge1<<<NE, EH>>>(edge_feats, W_e1, b_e1);
    k_w2cvt<<<(EH * DD * DD + 255) / 256, 256>>>(W_e2);
    k_edge2t<<<(NE + 127) / 128, 256, E2_SMEM_TOTAL>>>(b_e2);

    k_zero_rst<<<(NN * DD + 255) / 256, 256>>>();

    // message-passing steps
    for (int s = 0; s < NSTEPS; ++s) {
        k_msg<<<(NE + 7) / 8, 256>>>(src, dst);
        k_bnred<<<(NN + 127) / 128, 256>>>(conv_bias, bn_gamma, bn_beta);
        k_gru<<<(NN + 63) / 64, 192>>>(W_ih, W_hh, b_ih, b_hh,
                                       (float*)d_out, s == NSTEPS - 1);
    }
}